// round 6
// baseline (speedup 1.0000x reference)
#include <cuda_runtime.h>
#include <cuda_fp16.h>
#include <cstdint>

#define NFEAT   2048
#define NBATCH  8192
#define NFIELDS 8
#define FDIM    256
#define NL      64
#define ROWT    256
#define NTHREADS 256

// fp16 scratch (static device arrays -- no runtime allocation)
__device__ __half g_xh[(size_t)NBATCH * NFEAT];              // 32 MB, row-major [B, F]
__device__ __half g_vh[NFIELDS * NFIELDS * NL * FDIM];        // 2 MB, [s][t][l][k]

// ---------------- SMEM layout (81 KB -> 2 CTAs/SM) ----------------
// XA/XB: k-quarter X buffers [256 rows x 128B] = 32 KB each (row*128 + kin*2, SW128)
// VA/VB: k-quarter V buffers [64 rows x 128B] = 8 KB each
#define SM_DKS  0
#define SM_XA   1024
#define SM_XB   (SM_XA + 32768)
#define SM_VA   (SM_XB + 32768)
#define SM_VB   (SM_VA + 8192)
#define SM_TOTAL (SM_VB + 8192)   // 83968 B

#define SW128(off) ((off) ^ (((off) >> 3) & 0x70))

static __device__ __forceinline__ uint32_t smem_u32(const void* p) {
    uint32_t a;
    asm("{ .reg .u64 t; cvta.to.shared.u64 t, %1; cvt.u32.u64 %0, t; }" : "=r"(a) : "l"(p));
    return a;
}

#define CP_ASYNC16(dst, src) \
    asm volatile("cp.async.cg.shared.global [%0], [%1], 16;" :: "r"(dst), "l"(src))
#define CP_COMMIT() asm volatile("cp.async.commit_group;" ::: "memory")
#define CP_WAIT0()  asm volatile("cp.async.wait_group 0;" ::: "memory")
#define CP_WAIT1()  asm volatile("cp.async.wait_group 1;" ::: "memory")

static __device__ __forceinline__ void ldmx4(uint32_t addr, uint32_t& r0, uint32_t& r1,
                                             uint32_t& r2, uint32_t& r3) {
    asm volatile("ldmatrix.sync.aligned.m8n8.x4.shared.b16 {%0,%1,%2,%3}, [%4];"
                 : "=r"(r0), "=r"(r1), "=r"(r2), "=r"(r3) : "r"(addr));
}

static __device__ __forceinline__ void mma16816(float* d, uint32_t a0, uint32_t a1,
                                                uint32_t a2, uint32_t a3,
                                                uint32_t b0, uint32_t b1) {
    asm volatile(
        "mma.sync.aligned.m16n8k16.row.col.f32.f16.f16.f32 "
        "{%0,%1,%2,%3}, {%4,%5,%6,%7}, {%8,%9}, {%0,%1,%2,%3};"
        : "+f"(d[0]), "+f"(d[1]), "+f"(d[2]), "+f"(d[3])
        : "r"(a0), "r"(a1), "r"(a2), "r"(a3), "r"(b0), "r"(b1));
}

// Balanced unit groups: g0 = 4 pairs; g1..g8 = 3 pairs + 1 diag (7 half-units each)
__device__ const signed char U_S[36] = {
    0,0,0,0,  0,0,0,0,  1,1,1,1,  1,1,1,2,  2,2,2,3,  2,2,3,4,  3,3,3,5,  4,4,4,6,  5,5,6,7};
__device__ const signed char U_T[36] = {
    1,2,3,4,  5,6,7,0,  2,3,4,1,  5,6,7,2,  3,4,5,3,  6,7,4,4,  5,6,7,5,  5,6,7,6,  6,7,7,7};

// ------------------------------------------------------------------
__global__ void k_convert_x(const float* __restrict__ x) {
    size_t i = (size_t)blockIdx.x * blockDim.x + threadIdx.x;  // 8 floats each
    size_t n8 = (size_t)NBATCH * NFEAT / 8;
    if (i < n8) {
        const float4* src = (const float4*)x;
        float4 f0 = src[2 * i], f1 = src[2 * i + 1];
        __half2 h0 = __floats2half2_rn(f0.x, f0.y);
        __half2 h1 = __floats2half2_rn(f0.z, f0.w);
        __half2 h2 = __floats2half2_rn(f1.x, f1.y);
        __half2 h3 = __floats2half2_rn(f1.z, f1.w);
        uint4 o;
        o.x = *(uint32_t*)&h0; o.y = *(uint32_t*)&h1;
        o.z = *(uint32_t*)&h2; o.w = *(uint32_t*)&h3;
        ((uint4*)g_xh)[i] = o;
    }
}

__global__ void k_convert_v(const float* __restrict__ V, const float* __restrict__ b,
                            float* __restrict__ out) {
    int idx = blockIdx.x * blockDim.x + threadIdx.x;  // over 2048*8*64
    if (idx < NBATCH) out[idx] = b[0];
    if (idx < NFEAT * NFIELDS * NL) {
        int i = idx / (NFIELDS * NL);
        int rest = idx % (NFIELDS * NL);
        int t = rest / NL, l = rest % NL;
        int s = i >> 8, k = i & 255;
        g_vh[(((s * NFIELDS + t) * NL) + l) * FDIM + k] = __float2half_rn(V[idx]);
    }
}

// ------------------------------------------------------------------
// X quarter: 256 rows x 64 k = 32KB = 2048 x 16B; 256 thr -> 8 iters
static __device__ __forceinline__ void load_x_q(uint32_t sbuf, const __half* gsrc, int tid) {
    #pragma unroll
    for (int it = 0; it < 8; ++it) {
        int idx = tid + it * NTHREADS;
        int row = idx >> 3, c = idx & 7;
        uint32_t saddr = sbuf + SW128(row * 128 + c * 16);
        const char* gaddr = (const char*)gsrc + (size_t)row * (NFEAT * 2) + c * 16;
        CP_ASYNC16(saddr, gaddr);
    }
}

// V quarter: 64 rows x 64 k = 8KB = 512 x 16B; 2 iters
static __device__ __forceinline__ void load_v_q(uint32_t sbuf, const __half* gsrc, int tid) {
    #pragma unroll
    for (int it = 0; it < 2; ++it) {
        int idx = tid + it * NTHREADS;
        int row = idx >> 3, c = idx & 7;
        uint32_t saddr = sbuf + SW128(row * 128 + c * 16);
        const char* gaddr = (const char*)gsrc + row * (FDIM * 2) + c * 16;
        CP_ASYNC16(saddr, gaddr);
    }
}

// Quarter-K GEMM: acc += X_q(warp's 32 rows x 64k) @ V_q^T   (m32 n64 k64 per warp)
static __device__ __forceinline__ void gemm_q(uint32_t sx, uint32_t sv,
                                              int wid, int lane, float acc[2][8][4]) {
    const int arow = wid * 32 + (lane & 15);
    const int akoff = ((lane >> 4) << 3) * 2;               // 0 or 16 bytes
    const int brow_base = ((lane >> 4) << 3) + (lane & 7);
    const int bkoff = (((lane >> 3) & 1) << 3) * 2;         // 0 or 16 bytes

    #pragma unroll
    for (int k4 = 0; k4 < 4; ++k4) {
        const int kinb = k4 * 32;
        uint32_t a00, a01, a02, a03, a10, a11, a12, a13;
        ldmx4(sx + SW128(arow * 128 + kinb + akoff), a00, a01, a02, a03);
        ldmx4(sx + SW128((arow + 16) * 128 + kinb + akoff), a10, a11, a12, a13);
        #pragma unroll
        for (int vt = 0; vt < 4; ++vt) {
            uint32_t b0, b1, b2, b3;
            ldmx4(sv + SW128((vt * 16 + brow_base) * 128 + kinb + bkoff), b0, b1, b2, b3);
            mma16816(acc[0][2 * vt],     a00, a01, a02, a03, b0, b1);
            mma16816(acc[0][2 * vt + 1], a00, a01, a02, a03, b2, b3);
            mma16816(acc[1][2 * vt],     a10, a11, a12, a13, b0, b1);
            mma16816(acc[1][2 * vt + 1], a10, a11, a12, a13, b2, b3);
        }
    }
}

static __device__ __forceinline__ void zero_acc(float acc[2][8][4]) {
    #pragma unroll
    for (int m = 0; m < 2; ++m)
        #pragma unroll
        for (int n = 0; n < 8; ++n)
            #pragma unroll
            for (int j = 0; j < 4; ++j) acc[m][n][j] = 0.f;
}

// diag helper: dksq[k] = sum_l V_q[l,k]^2 for current V quarter (64 k's)
static __device__ __forceinline__ void diag_dks(const char* vsm, float* dksq, int tid) {
    if (tid < 64) {
        float a = 0.f;
        #pragma unroll 8
        for (int l = 0; l < NL; ++l) {
            float f = __half2float(*(const __half*)(vsm + SW128(l * 128 + tid * 2)));
            a += f * f;
        }
        dksq[tid] = a;
    }
}

// diag helper: per-row quarter contribution of (4*linear - q) using resident X quarter
static __device__ __forceinline__ void diag_qlin(const char* xsm, const float* dksq,
                                                 const float* wp_q, int wid, int lane,
                                                 float dql[4]) {
    const int kin0 = (lane & 3) * 16;
    const int rowb = wid * 32 + (lane >> 2);
    #pragma unroll
    for (int kk = 0; kk < 16; ++kk) {
        const int kin = kin0 + kk;
        float dk = dksq[kin];
        float wv = __ldg(wp_q + kin);
        #pragma unroll
        for (int mf = 0; mf < 2; ++mf)
            #pragma unroll
            for (int h = 0; h < 2; ++h) {
                int row = rowb + mf * 16 + h * 8;
                float xv = __half2float(*(const __half*)(xsm + SW128(row * 128 + kin * 2)));
                dql[mf * 2 + h] += xv * (4.f * wv - xv * dk);
            }
    }
}

__global__ __launch_bounds__(NTHREADS, 2)
void ffm_main(const float* __restrict__ w, float* __restrict__ out) {
    extern __shared__ char smem[];
    const uint32_t sb = smem_u32(smem);
    const uint32_t XA = sb + SM_XA, XB = sb + SM_XB, VA = sb + SM_VA, VB = sb + SM_VB;
    const int tid = threadIdx.x;
    const int wid = tid >> 5;
    const int lane = tid & 31;
    const int r0 = blockIdx.x * ROWT;
    float* dksq = (float*)(smem + SM_DKS);

    float acc_int[4] = {0.f, 0.f, 0.f, 0.f};   // slots: mf*2 + h; row = wid*32+mf*16+(lane>>2)+h*8

    for (int uu = 0; uu < 4; ++uu) {
        const int u = blockIdx.y * 4 + uu;
        const int s = U_S[u], t = U_T[u];
        const __half* xs = g_xh + (size_t)r0 * NFEAT + s * FDIM;
        const __half* xt = g_xh + (size_t)r0 * NFEAT + t * FDIM;
        const __half* vst = g_vh + (size_t)((s * NFIELDS + t) * NL) * FDIM;
        const __half* vts = g_vh + (size_t)((t * NFIELDS + s) * NL) * FDIM;

        float acc[2][8][4];
        zero_acc(acc);
        float p[4] = {0.f, 0.f, 0.f, 0.f};

        if (s != t) {
            // ---- pair unit: GEMM1 = X_s @ V_st^T, GEMM2 = X_t @ V_ts^T ----
            load_x_q(XA, xs, tid);       load_v_q(VA, vst, tid);       CP_COMMIT();
            load_x_q(XB, xs + 64, tid);  load_v_q(VB, vst + 64, tid);  CP_COMMIT();
            CP_WAIT1(); __syncthreads();
            gemm_q(XA, VA, wid, lane, acc);                       // q0
            __syncthreads();
            load_x_q(XA, xs + 128, tid); load_v_q(VA, vst + 128, tid); CP_COMMIT();
            CP_WAIT1(); __syncthreads();
            gemm_q(XB, VB, wid, lane, acc);                       // q1
            __syncthreads();
            load_x_q(XB, xs + 192, tid); load_v_q(VB, vst + 192, tid); CP_COMMIT();
            CP_WAIT1(); __syncthreads();
            gemm_q(XA, VA, wid, lane, acc);                       // q2
            __syncthreads();
            load_x_q(XA, xt, tid);       load_v_q(VA, vts, tid);       CP_COMMIT();
            CP_WAIT1(); __syncthreads();
            gemm_q(XB, VB, wid, lane, acc);                       // q3 -> M1 complete

            // stash M1 as fp16 in registers, reset acc for GEMM2
            uint32_t m1[2][8][2];
            #pragma unroll
            for (int mf = 0; mf < 2; ++mf)
                #pragma unroll
                for (int nf = 0; nf < 8; ++nf) {
                    __half2 lo = __floats2half2_rn(acc[mf][nf][0], acc[mf][nf][1]);
                    __half2 hi = __floats2half2_rn(acc[mf][nf][2], acc[mf][nf][3]);
                    m1[mf][nf][0] = *(uint32_t*)&lo;
                    m1[mf][nf][1] = *(uint32_t*)&hi;
                    acc[mf][nf][0] = 0.f; acc[mf][nf][1] = 0.f;
                    acc[mf][nf][2] = 0.f; acc[mf][nf][3] = 0.f;
                }

            __syncthreads();
            load_x_q(XB, xt + 64, tid);  load_v_q(VB, vts + 64, tid);  CP_COMMIT();
            CP_WAIT1(); __syncthreads();
            gemm_q(XA, VA, wid, lane, acc);                       // G2 q0
            __syncthreads();
            load_x_q(XA, xt + 128, tid); load_v_q(VA, vts + 128, tid); CP_COMMIT();
            CP_WAIT1(); __syncthreads();
            gemm_q(XB, VB, wid, lane, acc);                       // G2 q1
            __syncthreads();
            load_x_q(XB, xt + 192, tid); load_v_q(VB, vts + 192, tid); CP_COMMIT();
            CP_WAIT1(); __syncthreads();
            gemm_q(XA, VA, wid, lane, acc);                       // G2 q2
            CP_WAIT0(); __syncthreads();
            gemm_q(XB, VB, wid, lane, acc);                       // G2 q3

            // dot(M1, M2), counted twice (ordered pairs)
            #pragma unroll
            for (int mf = 0; mf < 2; ++mf)
                #pragma unroll
                for (int nf = 0; nf < 8; ++nf) {
                    float2 lo = __half22float2(*(__half2*)&m1[mf][nf][0]);
                    float2 hi = __half22float2(*(__half2*)&m1[mf][nf][1]);
                    p[mf * 2 + 0] += lo.x * acc[mf][nf][0] + lo.y * acc[mf][nf][1];
                    p[mf * 2 + 1] += hi.x * acc[mf][nf][2] + hi.y * acc[mf][nf][3];
                }
            #pragma unroll
            for (int i = 0; i < 4; ++i) p[i] *= 2.f;
        } else {
            // ---- diag unit: one GEMM + q/linear folded per quarter ----
            float dql[4] = {0.f, 0.f, 0.f, 0.f};
            const float* wp = w + s * FDIM;

            load_x_q(XA, xs, tid);       load_v_q(VA, vst, tid);       CP_COMMIT();
            load_x_q(XB, xs + 64, tid);  load_v_q(VB, vst + 64, tid);  CP_COMMIT();
            CP_WAIT1(); __syncthreads();
            gemm_q(XA, VA, wid, lane, acc);
            diag_dks(smem + SM_VA, dksq, tid);
            __syncthreads();
            diag_qlin(smem + SM_XA, dksq, wp, wid, lane, dql);
            __syncthreads();
            load_x_q(XA, xs + 128, tid); load_v_q(VA, vst + 128, tid); CP_COMMIT();
            CP_WAIT1(); __syncthreads();
            gemm_q(XB, VB, wid, lane, acc);
            diag_dks(smem + SM_VB, dksq, tid);
            __syncthreads();
            diag_qlin(smem + SM_XB, dksq, wp + 64, wid, lane, dql);
            __syncthreads();
            load_x_q(XB, xs + 192, tid); load_v_q(VB, vst + 192, tid); CP_COMMIT();
            CP_WAIT1(); __syncthreads();
            gemm_q(XA, VA, wid, lane, acc);
            diag_dks(smem + SM_VA, dksq, tid);
            __syncthreads();
            diag_qlin(smem + SM_XA, dksq, wp + 128, wid, lane, dql);
            CP_WAIT0(); __syncthreads();
            gemm_q(XB, VB, wid, lane, acc);
            diag_dks(smem + SM_VB, dksq, tid);
            __syncthreads();
            diag_qlin(smem + SM_XB, dksq, wp + 192, wid, lane, dql);

            // self dot minus q, plus 4*linear (all in dql)
            #pragma unroll
            for (int mf = 0; mf < 2; ++mf)
                #pragma unroll
                for (int nf = 0; nf < 8; ++nf) {
                    p[mf * 2 + 0] += acc[mf][nf][0] * acc[mf][nf][0] +
                                     acc[mf][nf][1] * acc[mf][nf][1];
                    p[mf * 2 + 1] += acc[mf][nf][2] * acc[mf][nf][2] +
                                     acc[mf][nf][3] * acc[mf][nf][3];
                }
            #pragma unroll
            for (int i = 0; i < 4; ++i) p[i] += dql[i];
        }

        // reduce over the 4 lanes sharing each row, accumulate
        #pragma unroll
        for (int i = 0; i < 4; ++i) {
            p[i] += __shfl_xor_sync(0xFFFFFFFFu, p[i], 1);
            p[i] += __shfl_xor_sync(0xFFFFFFFFu, p[i], 2);
            acc_int[i] += p[i];
        }
        __syncthreads();   // before next unit's loads overwrite tiles
    }

    if ((lane & 3) == 0) {
        #pragma unroll
        for (int mf = 0; mf < 2; ++mf)
            #pragma unroll
            for (int h = 0; h < 2; ++h) {
                int row = r0 + wid * 32 + mf * 16 + (lane >> 2) + h * 8;
                atomicAdd(out + row, 0.25f * acc_int[mf * 2 + h]);
            }
    }
}

// ------------------------------------------------------------------
extern "C" void kernel_launch(void* const* d_in, const int* in_sizes, int n_in,
                              void* d_out, int out_size) {
    const float* x = (const float*)d_in[0];
    const float* b = (const float*)d_in[1];
    const float* w = (const float*)d_in[2];
    const float* V = (const float*)d_in[3];
    float* out = (float*)d_out;

    cudaFuncSetAttribute(ffm_main, cudaFuncAttributeMaxDynamicSharedMemorySize, SM_TOTAL);

    {
        size_t n8 = (size_t)NBATCH * NFEAT / 8;
        k_convert_x<<<(unsigned)((n8 + 255) / 256), 256>>>(x);
    }
    k_convert_v<<<(NFEAT * NFIELDS * NL + 255) / 256, 256>>>(V, b, out);
    ffm_main<<<dim3(NBATCH / ROWT, 9), NTHREADS, SM_TOTAL>>>(w, out);
}

// round 7
// speedup vs baseline: 1.0184x; 1.0184x over previous
#include <cuda_runtime.h>
#include <cuda_fp16.h>
#include <cstdint>

#define NFEAT   2048
#define NBATCH  8192
#define NFIELDS 8
#define FDIM    256
#define NL      64
#define ROWT    256
#define NTHREADS 256

// fp16 scratch (static device arrays -- no runtime allocation)
__device__ __half g_xh[(size_t)NBATCH * NFEAT];              // 32 MB, row-major [B, F]
__device__ __half g_vh[NFIELDS * NFIELDS * NL * FDIM];        // 2 MB, [s][t][l][k]

// ---------------- SMEM layout (113 KB -> 2 CTAs/SM) ----------------
// XA/XB: k-quarter X buffers [256 rows x 128B] = 32 KB each
// VA/VB: k-quarter V buffers [64 rows x 128B] = 8 KB each
// M1: fp16 stash of GEMM1 fragments, 32 slots x 256 threads x 4B = 32 KB
#define SM_DKS  0
#define SM_XA   1024
#define SM_XB   (SM_XA + 32768)
#define SM_VA   (SM_XB + 32768)
#define SM_VB   (SM_VA + 8192)
#define SM_M1   (SM_VB + 8192)
#define SM_TOTAL (SM_M1 + 32768)   // 115712 B = 113.0 KB

#define SW128(off) ((off) ^ (((off) >> 3) & 0x70))

static __device__ __forceinline__ uint32_t smem_u32(const void* p) {
    uint32_t a;
    asm("{ .reg .u64 t; cvta.to.shared.u64 t, %1; cvt.u32.u64 %0, t; }" : "=r"(a) : "l"(p));
    return a;
}

#define CP_ASYNC16(dst, src) \
    asm volatile("cp.async.cg.shared.global [%0], [%1], 16;" :: "r"(dst), "l"(src))
#define CP_COMMIT() asm volatile("cp.async.commit_group;" ::: "memory")
#define CP_WAIT0()  asm volatile("cp.async.wait_group 0;" ::: "memory")
#define CP_WAIT1()  asm volatile("cp.async.wait_group 1;" ::: "memory")

static __device__ __forceinline__ void ldmx4(uint32_t addr, uint32_t& r0, uint32_t& r1,
                                             uint32_t& r2, uint32_t& r3) {
    asm volatile("ldmatrix.sync.aligned.m8n8.x4.shared.b16 {%0,%1,%2,%3}, [%4];"
                 : "=r"(r0), "=r"(r1), "=r"(r2), "=r"(r3) : "r"(addr));
}

static __device__ __forceinline__ void mma16816(float* d, uint32_t a0, uint32_t a1,
                                                uint32_t a2, uint32_t a3,
                                                uint32_t b0, uint32_t b1) {
    asm volatile(
        "mma.sync.aligned.m16n8k16.row.col.f32.f16.f16.f32 "
        "{%0,%1,%2,%3}, {%4,%5,%6,%7}, {%8,%9}, {%0,%1,%2,%3};"
        : "+f"(d[0]), "+f"(d[1]), "+f"(d[2]), "+f"(d[3])
        : "r"(a0), "r"(a1), "r"(a2), "r"(a3), "r"(b0), "r"(b1));
}

// Balanced unit groups: g0 = 4 pairs; g1..g8 = 3 pairs + 1 diag (7 half-units each)
__device__ const signed char U_S[36] = {
    0,0,0,0,  0,0,0,0,  1,1,1,1,  1,1,1,2,  2,2,2,3,  2,2,3,4,  3,3,3,5,  4,4,4,6,  5,5,6,7};
__device__ const signed char U_T[36] = {
    1,2,3,4,  5,6,7,0,  2,3,4,1,  5,6,7,2,  3,4,5,3,  6,7,4,4,  5,6,7,5,  5,6,7,6,  6,7,7,7};

// ------------------------------------------------------------------
__global__ void k_convert_x(const float* __restrict__ x) {
    size_t i = (size_t)blockIdx.x * blockDim.x + threadIdx.x;  // 8 floats each
    size_t n8 = (size_t)NBATCH * NFEAT / 8;
    if (i < n8) {
        const float4* src = (const float4*)x;
        float4 f0 = src[2 * i], f1 = src[2 * i + 1];
        __half2 h0 = __floats2half2_rn(f0.x, f0.y);
        __half2 h1 = __floats2half2_rn(f0.z, f0.w);
        __half2 h2 = __floats2half2_rn(f1.x, f1.y);
        __half2 h3 = __floats2half2_rn(f1.z, f1.w);
        uint4 o;
        o.x = *(uint32_t*)&h0; o.y = *(uint32_t*)&h1;
        o.z = *(uint32_t*)&h2; o.w = *(uint32_t*)&h3;
        ((uint4*)g_xh)[i] = o;
    }
}

__global__ void k_convert_v(const float* __restrict__ V, const float* __restrict__ b,
                            float* __restrict__ out) {
    int idx = blockIdx.x * blockDim.x + threadIdx.x;  // over 2048*8*64
    if (idx < NBATCH) out[idx] = b[0];
    if (idx < NFEAT * NFIELDS * NL) {
        int i = idx / (NFIELDS * NL);
        int rest = idx % (NFIELDS * NL);
        int t = rest / NL, l = rest % NL;
        int s = i >> 8, k = i & 255;
        g_vh[(((s * NFIELDS + t) * NL) + l) * FDIM + k] = __float2half_rn(V[idx]);
    }
}

// ------------------------------------------------------------------
// X quarter: 256 rows x 64 k = 32KB = 2048 x 16B; 256 thr -> 8 iters
static __device__ __forceinline__ void load_x_q(uint32_t sbuf, const __half* gsrc, int tid) {
    #pragma unroll
    for (int it = 0; it < 8; ++it) {
        int idx = tid + it * NTHREADS;
        int row = idx >> 3, c = idx & 7;
        uint32_t saddr = sbuf + SW128(row * 128 + c * 16);
        const char* gaddr = (const char*)gsrc + (size_t)row * (NFEAT * 2) + c * 16;
        CP_ASYNC16(saddr, gaddr);
    }
}

// V quarter: 64 rows x 64 k = 8KB = 512 x 16B; 2 iters
static __device__ __forceinline__ void load_v_q(uint32_t sbuf, const __half* gsrc, int tid) {
    #pragma unroll
    for (int it = 0; it < 2; ++it) {
        int idx = tid + it * NTHREADS;
        int row = idx >> 3, c = idx & 7;
        uint32_t saddr = sbuf + SW128(row * 128 + c * 16);
        const char* gaddr = (const char*)gsrc + row * (FDIM * 2) + c * 16;
        CP_ASYNC16(saddr, gaddr);
    }
}

// Quarter-K GEMM: acc += X_q(warp's 32 rows x 64k) @ V_q^T   (m32 n64 k64 per warp)
static __device__ __forceinline__ void gemm_q(uint32_t sx, uint32_t sv,
                                              int wid, int lane, float acc[2][8][4]) {
    const int arow = wid * 32 + (lane & 15);
    const int akoff = ((lane >> 4) << 3) * 2;               // 0 or 16 bytes
    const int brow_base = ((lane >> 4) << 3) + (lane & 7);
    const int bkoff = (((lane >> 3) & 1) << 3) * 2;         // 0 or 16 bytes

    #pragma unroll
    for (int k4 = 0; k4 < 4; ++k4) {
        const int kinb = k4 * 32;
        uint32_t a00, a01, a02, a03, a10, a11, a12, a13;
        ldmx4(sx + SW128(arow * 128 + kinb + akoff), a00, a01, a02, a03);
        ldmx4(sx + SW128((arow + 16) * 128 + kinb + akoff), a10, a11, a12, a13);
        #pragma unroll
        for (int vt = 0; vt < 4; ++vt) {
            uint32_t b0, b1, b2, b3;
            ldmx4(sv + SW128((vt * 16 + brow_base) * 128 + kinb + bkoff), b0, b1, b2, b3);
            mma16816(acc[0][2 * vt],     a00, a01, a02, a03, b0, b1);
            mma16816(acc[0][2 * vt + 1], a00, a01, a02, a03, b2, b3);
            mma16816(acc[1][2 * vt],     a10, a11, a12, a13, b0, b1);
            mma16816(acc[1][2 * vt + 1], a10, a11, a12, a13, b2, b3);
        }
    }
}

static __device__ __forceinline__ void zero_acc(float acc[2][8][4]) {
    #pragma unroll
    for (int m = 0; m < 2; ++m)
        #pragma unroll
        for (int n = 0; n < 8; ++n)
            #pragma unroll
            for (int j = 0; j < 4; ++j) acc[m][n][j] = 0.f;
}

// diag helper: dksq[k] = sum_l V_q[l,k]^2 for current V quarter (64 k's)
static __device__ __forceinline__ void diag_dks(const char* vsm, float* dksq, int tid) {
    if (tid < 64) {
        float a = 0.f;
        #pragma unroll 8
        for (int l = 0; l < NL; ++l) {
            float f = __half2float(*(const __half*)(vsm + SW128(l * 128 + tid * 2)));
            a += f * f;
        }
        dksq[tid] = a;
    }
}

// diag helper: per-row quarter contribution of (4*linear - q) using resident X quarter
static __device__ __forceinline__ void diag_qlin(const char* xsm, const float* dksq,
                                                 const float* wp_q, int wid, int lane,
                                                 float dql[4]) {
    const int kin0 = (lane & 3) * 16;
    const int rowb = wid * 32 + (lane >> 2);
    #pragma unroll
    for (int kk = 0; kk < 16; ++kk) {
        const int kin = kin0 + kk;
        float dk = dksq[kin];
        float wv = __ldg(wp_q + kin);
        #pragma unroll
        for (int mf = 0; mf < 2; ++mf)
            #pragma unroll
            for (int h = 0; h < 2; ++h) {
                int row = rowb + mf * 16 + h * 8;
                float xv = __half2float(*(const __half*)(xsm + SW128(row * 128 + kin * 2)));
                dql[mf * 2 + h] += xv * (4.f * wv - xv * dk);
            }
    }
}

__global__ __launch_bounds__(NTHREADS, 2)
void ffm_main(const float* __restrict__ w, float* __restrict__ out) {
    extern __shared__ char smem[];
    const uint32_t sb = smem_u32(smem);
    const uint32_t XA = sb + SM_XA, XB = sb + SM_XB, VA = sb + SM_VA, VB = sb + SM_VB;
    const int tid = threadIdx.x;
    const int wid = tid >> 5;
    const int lane = tid & 31;
    const int r0 = blockIdx.x * ROWT;
    float* dksq = (float*)(smem + SM_DKS);
    uint32_t* m1buf = (uint32_t*)(smem + SM_M1);   // [32 slots][256 threads]

    float acc_int[4] = {0.f, 0.f, 0.f, 0.f};   // slots: mf*2 + h; row = wid*32+mf*16+(lane>>2)+h*8

    for (int uu = 0; uu < 4; ++uu) {
        const int u = blockIdx.y * 4 + uu;
        const int s = U_S[u], t = U_T[u];
        const __half* xs = g_xh + (size_t)r0 * NFEAT + s * FDIM;
        const __half* xt = g_xh + (size_t)r0 * NFEAT + t * FDIM;
        const __half* vst = g_vh + (size_t)((s * NFIELDS + t) * NL) * FDIM;
        const __half* vts = g_vh + (size_t)((t * NFIELDS + s) * NL) * FDIM;

        float acc[2][8][4];
        zero_acc(acc);
        float p[4] = {0.f, 0.f, 0.f, 0.f};

        if (s != t) {
            // ---- pair unit: GEMM1 = X_s @ V_st^T, GEMM2 = X_t @ V_ts^T ----
            load_x_q(XA, xs, tid);       load_v_q(VA, vst, tid);       CP_COMMIT();
            load_x_q(XB, xs + 64, tid);  load_v_q(VB, vst + 64, tid);  CP_COMMIT();
            CP_WAIT1(); __syncthreads();
            gemm_q(XA, VA, wid, lane, acc);                       // q0
            __syncthreads();
            load_x_q(XA, xs + 128, tid); load_v_q(VA, vst + 128, tid); CP_COMMIT();
            CP_WAIT1(); __syncthreads();
            gemm_q(XB, VB, wid, lane, acc);                       // q1
            __syncthreads();
            load_x_q(XB, xs + 192, tid); load_v_q(VB, vst + 192, tid); CP_COMMIT();
            CP_WAIT1(); __syncthreads();
            gemm_q(XA, VA, wid, lane, acc);                       // q2
            __syncthreads();
            load_x_q(XA, xt, tid);       load_v_q(VA, vts, tid);       CP_COMMIT();
            CP_WAIT1(); __syncthreads();
            gemm_q(XB, VB, wid, lane, acc);                       // q3 -> M1 complete

            // stash M1 as fp16 in SMEM (own slots; no cross-thread sharing -> no sync)
            #pragma unroll
            for (int mf = 0; mf < 2; ++mf)
                #pragma unroll
                for (int nf = 0; nf < 8; ++nf) {
                    __half2 lo = __floats2half2_rn(acc[mf][nf][0], acc[mf][nf][1]);
                    __half2 hi = __floats2half2_rn(acc[mf][nf][2], acc[mf][nf][3]);
                    m1buf[(mf * 16 + nf * 2 + 0) * NTHREADS + tid] = *(uint32_t*)&lo;
                    m1buf[(mf * 16 + nf * 2 + 1) * NTHREADS + tid] = *(uint32_t*)&hi;
                    acc[mf][nf][0] = 0.f; acc[mf][nf][1] = 0.f;
                    acc[mf][nf][2] = 0.f; acc[mf][nf][3] = 0.f;
                }

            __syncthreads();
            load_x_q(XB, xt + 64, tid);  load_v_q(VB, vts + 64, tid);  CP_COMMIT();
            CP_WAIT1(); __syncthreads();
            gemm_q(XA, VA, wid, lane, acc);                       // G2 q0
            __syncthreads();
            load_x_q(XA, xt + 128, tid); load_v_q(VA, vts + 128, tid); CP_COMMIT();
            CP_WAIT1(); __syncthreads();
            gemm_q(XB, VB, wid, lane, acc);                       // G2 q1
            __syncthreads();
            load_x_q(XB, xt + 192, tid); load_v_q(VB, vts + 192, tid); CP_COMMIT();
            CP_WAIT1(); __syncthreads();
            gemm_q(XA, VA, wid, lane, acc);                       // G2 q2
            CP_WAIT0(); __syncthreads();
            gemm_q(XB, VB, wid, lane, acc);                       // G2 q3

            // dot(M1, M2), counted twice (ordered pairs)
            #pragma unroll
            for (int mf = 0; mf < 2; ++mf)
                #pragma unroll
                for (int nf = 0; nf < 8; ++nf) {
                    uint32_t ulo = m1buf[(mf * 16 + nf * 2 + 0) * NTHREADS + tid];
                    uint32_t uhi = m1buf[(mf * 16 + nf * 2 + 1) * NTHREADS + tid];
                    float2 lo = __half22float2(*(__half2*)&ulo);
                    float2 hi = __half22float2(*(__half2*)&uhi);
                    p[mf * 2 + 0] += lo.x * acc[mf][nf][0] + lo.y * acc[mf][nf][1];
                    p[mf * 2 + 1] += hi.x * acc[mf][nf][2] + hi.y * acc[mf][nf][3];
                }
            #pragma unroll
            for (int i = 0; i < 4; ++i) p[i] *= 2.f;
        } else {
            // ---- diag unit: one GEMM + q/linear folded per quarter ----
            float dql[4] = {0.f, 0.f, 0.f, 0.f};
            const float* wp = w + s * FDIM;

            load_x_q(XA, xs, tid);       load_v_q(VA, vst, tid);       CP_COMMIT();
            load_x_q(XB, xs + 64, tid);  load_v_q(VB, vst + 64, tid);  CP_COMMIT();
            CP_WAIT1(); __syncthreads();
            gemm_q(XA, VA, wid, lane, acc);
            diag_dks(smem + SM_VA, dksq, tid);
            __syncthreads();
            diag_qlin(smem + SM_XA, dksq, wp, wid, lane, dql);
            __syncthreads();
            load_x_q(XA, xs + 128, tid); load_v_q(VA, vst + 128, tid); CP_COMMIT();
            CP_WAIT1(); __syncthreads();
            gemm_q(XB, VB, wid, lane, acc);
            diag_dks(smem + SM_VB, dksq, tid);
            __syncthreads();
            diag_qlin(smem + SM_XB, dksq, wp + 64, wid, lane, dql);
            __syncthreads();
            load_x_q(XB, xs + 192, tid); load_v_q(VB, vst + 192, tid); CP_COMMIT();
            CP_WAIT1(); __syncthreads();
            gemm_q(XA, VA, wid, lane, acc);
            diag_dks(smem + SM_VA, dksq, tid);
            __syncthreads();
            diag_qlin(smem + SM_XA, dksq, wp + 128, wid, lane, dql);
            CP_WAIT0(); __syncthreads();
            gemm_q(XB, VB, wid, lane, acc);
            diag_dks(smem + SM_VB, dksq, tid);
            __syncthreads();
            diag_qlin(smem + SM_XB, dksq, wp + 192, wid, lane, dql);

            // self dot minus q, plus 4*linear (all in dql)
            #pragma unroll
            for (int mf = 0; mf < 2; ++mf)
                #pragma unroll
                for (int nf = 0; nf < 8; ++nf) {
                    p[mf * 2 + 0] += acc[mf][nf][0] * acc[mf][nf][0] +
                                     acc[mf][nf][1] * acc[mf][nf][1];
                    p[mf * 2 + 1] += acc[mf][nf][2] * acc[mf][nf][2] +
                                     acc[mf][nf][3] * acc[mf][nf][3];
                }
            #pragma unroll
            for (int i = 0; i < 4; ++i) p[i] += dql[i];
        }

        // reduce over the 4 lanes sharing each row, accumulate
        #pragma unroll
        for (int i = 0; i < 4; ++i) {
            p[i] += __shfl_xor_sync(0xFFFFFFFFu, p[i], 1);
            p[i] += __shfl_xor_sync(0xFFFFFFFFu, p[i], 2);
            acc_int[i] += p[i];
        }
        __syncthreads();   // before next unit's loads overwrite tiles
    }

    if ((lane & 3) == 0) {
        #pragma unroll
        for (int mf = 0; mf < 2; ++mf)
            #pragma unroll
            for (int h = 0; h < 2; ++h) {
                int row = r0 + wid * 32 + mf * 16 + (lane >> 2) + h * 8;
                atomicAdd(out + row, 0.25f * acc_int[mf * 2 + h]);
            }
    }
}

// ------------------------------------------------------------------
extern "C" void kernel_launch(void* const* d_in, const int* in_sizes, int n_in,
                              void* d_out, int out_size) {
    const float* x = (const float*)d_in[0];
    const float* b = (const float*)d_in[1];
    const float* w = (const float*)d_in[2];
    const float* V = (const float*)d_in[3];
    float* out = (float*)d_out;

    cudaFuncSetAttribute(ffm_main, cudaFuncAttributeMaxDynamicSharedMemorySize, SM_TOTAL);

    {
        size_t n8 = (size_t)NBATCH * NFEAT / 8;
        k_convert_x<<<(unsigned)((n8 + 255) / 256), 256>>>(x);
    }
    k_convert_v<<<(NFEAT * NFIELDS * NL + 255) / 256, 256>>>(V, b, out);
    ffm_main<<<dim3(NBATCH / ROWT, 9), NTHREADS, SM_TOTAL>>>(w, out);
}

// round 8
// speedup vs baseline: 1.0652x; 1.0460x over previous
#include <cuda_runtime.h>
#include <cuda_fp16.h>
#include <cstdint>

#define NFEAT   2048
#define NBATCH  8192
#define NFIELDS 8
#define FDIM    256
#define NL      64
#define ROWT    128
#define NTHREADS 256

// fp16 scratch (static device arrays -- no runtime allocation)
__device__ __half g_xh[(size_t)NBATCH * NFEAT];              // 32 MB, row-major [B, F]
__device__ __half g_vh[NFIELDS * NFIELDS * NL * FDIM];        // 2 MB, [s][t][l][k]

// ---------------- SMEM layout (97 KB -> 2 CTAs/SM) ----------------
// XS/XT: 2 k-quarter bufs x [128 rows x 128B] = 16 KB each buf
// VS/VT: 2 bufs x 2 h-halves x [32 l-rows x 128B] = 4 KB per (buf,h)
#define SM_DKS  0
#define SM_XS   1024
#define SM_XT   (SM_XS + 32768)
#define SM_VS   (SM_XT + 32768)
#define SM_VT   (SM_VS + 16384)
#define SM_TOTAL (SM_VT + 16384)   // 99328 B

#define SW128(off) ((off) ^ (((off) >> 3) & 0x70))

static __device__ __forceinline__ uint32_t smem_u32(const void* p) {
    uint32_t a;
    asm("{ .reg .u64 t; cvta.to.shared.u64 t, %1; cvt.u32.u64 %0, t; }" : "=r"(a) : "l"(p));
    return a;
}

#define CP_ASYNC16(dst, src) \
    asm volatile("cp.async.cg.shared.global [%0], [%1], 16;" :: "r"(dst), "l"(src))
#define CP_COMMIT() asm volatile("cp.async.commit_group;" ::: "memory")
#define CP_WAIT0()  asm volatile("cp.async.wait_group 0;" ::: "memory")
#define CP_WAIT1()  asm volatile("cp.async.wait_group 1;" ::: "memory")

// named barriers: 1+p (64 thr, pair scope), 5+h (128 thr, h-group scope)
#define BARX(id, cnt) asm volatile("bar.sync %0, %1;" :: "r"(id), "r"(cnt) : "memory")

static __device__ __forceinline__ void ldmx4(uint32_t addr, uint32_t& r0, uint32_t& r1,
                                             uint32_t& r2, uint32_t& r3) {
    asm volatile("ldmatrix.sync.aligned.m8n8.x4.shared.b16 {%0,%1,%2,%3}, [%4];"
                 : "=r"(r0), "=r"(r1), "=r"(r2), "=r"(r3) : "r"(addr));
}

static __device__ __forceinline__ void mma16816(float* d, uint32_t a0, uint32_t a1,
                                                uint32_t a2, uint32_t a3,
                                                uint32_t b0, uint32_t b1) {
    asm volatile(
        "mma.sync.aligned.m16n8k16.row.col.f32.f16.f16.f32 "
        "{%0,%1,%2,%3}, {%4,%5,%6,%7}, {%8,%9}, {%0,%1,%2,%3};"
        : "+f"(d[0]), "+f"(d[1]), "+f"(d[2]), "+f"(d[3])
        : "r"(a0), "r"(a1), "r"(a2), "r"(a3), "r"(b0), "r"(b1));
}

// Balanced unit groups: g0 = 4 pairs; g1..g8 = 3 pairs + 1 diag
__device__ const signed char U_S[36] = {
    0,0,0,0,  0,0,0,0,  1,1,1,1,  1,1,1,2,  2,2,2,3,  2,2,3,4,  3,3,3,5,  4,4,4,6,  5,5,6,7};
__device__ const signed char U_T[36] = {
    1,2,3,4,  5,6,7,0,  2,3,4,1,  5,6,7,2,  3,4,5,3,  6,7,4,4,  5,6,7,5,  5,6,7,6,  6,7,7,7};

// ------------------------------------------------------------------
__global__ void k_convert_x(const float* __restrict__ x) {
    size_t i = (size_t)blockIdx.x * blockDim.x + threadIdx.x;  // 8 floats each
    size_t n8 = (size_t)NBATCH * NFEAT / 8;
    if (i < n8) {
        const float4* src = (const float4*)x;
        float4 f0 = src[2 * i], f1 = src[2 * i + 1];
        __half2 h0 = __floats2half2_rn(f0.x, f0.y);
        __half2 h1 = __floats2half2_rn(f0.z, f0.w);
        __half2 h2 = __floats2half2_rn(f1.x, f1.y);
        __half2 h3 = __floats2half2_rn(f1.z, f1.w);
        uint4 o;
        o.x = *(uint32_t*)&h0; o.y = *(uint32_t*)&h1;
        o.z = *(uint32_t*)&h2; o.w = *(uint32_t*)&h3;
        ((uint4*)g_xh)[i] = o;
    }
}

__global__ void k_convert_v(const float* __restrict__ V, const float* __restrict__ b,
                            float* __restrict__ out) {
    int idx = blockIdx.x * blockDim.x + threadIdx.x;
    if (idx < NBATCH) out[idx] = b[0];
    if (idx < NFEAT * NFIELDS * NL) {
        int i = idx / (NFIELDS * NL);
        int rest = idx % (NFIELDS * NL);
        int t = rest / NL, l = rest % NL;
        int s = i >> 8, k = i & 255;
        g_vh[(((s * NFIELDS + t) * NL) + l) * FDIM + k] = __float2half_rn(V[idx]);
    }
}

// ------------------------------------------------------------------
// X quarter slice for this thread's pair: rows p*32+h*16..+16 x 128B; 4 x 16B per thread
static __device__ __forceinline__ void load_xq(uint32_t sbuf, const __half* gsrc,
                                               int p, int h, int lane) {
    #pragma unroll
    for (int it = 0; it < 4; ++it) {
        int tsk = lane + it * 32;                 // 0..127
        int row = p * 32 + h * 16 + (tsk >> 3);
        int c = tsk & 7;
        uint32_t sa = sbuf + SW128(row * 128 + c * 16);
        const char* ga = (const char*)gsrc + (size_t)row * (NFEAT * 2) + c * 16;
        CP_ASYNC16(sa, ga);
    }
}

// V half-quarter for this h-group: 32 l-rows x 128B; 2 x 16B per thread
// gsrc pre-offset to [l = h*32][k = q*64]
static __device__ __forceinline__ void load_vq(uint32_t sbuf, const __half* gsrc,
                                               int p, int lane) {
    #pragma unroll
    for (int it = 0; it < 2; ++it) {
        int tsk = p * 32 + lane + it * 128;       // 0..255, disjoint across h-group
        int row = tsk >> 3;
        int c = tsk & 7;
        uint32_t sa = sbuf + SW128(row * 128 + c * 16);
        const char* ga = (const char*)gsrc + (size_t)row * (FDIM * 2) + c * 16;
        CP_ASYNC16(sa, ga);
    }
}

// Quarter GEMM: acc += X_q(warp's 32 rows x 64k) @ V_halfq^T   (m32 x n32 x k64)
static __device__ __forceinline__ void gemm32(uint32_t sx, uint32_t sv,
                                              int p, int lane, float acc[2][4][4]) {
    const int arow = p * 32 + (lane & 15);
    const int ak = ((lane >> 4) << 3) * 2;
    const int brow = ((lane >> 4) << 3) + (lane & 7);
    const int bk = (((lane >> 3) & 1) << 3) * 2;
    #pragma unroll
    for (int k4 = 0; k4 < 4; ++k4) {
        const int kb = k4 * 32;
        uint32_t a00, a01, a02, a03, a10, a11, a12, a13;
        ldmx4(sx + SW128(arow * 128 + kb + ak), a00, a01, a02, a03);
        ldmx4(sx + SW128((arow + 16) * 128 + kb + ak), a10, a11, a12, a13);
        #pragma unroll
        for (int vt = 0; vt < 2; ++vt) {
            uint32_t b0, b1, b2, b3;
            ldmx4(sv + SW128((vt * 16 + brow) * 128 + kb + bk), b0, b1, b2, b3);
            mma16816(acc[0][2 * vt],     a00, a01, a02, a03, b0, b1);
            mma16816(acc[0][2 * vt + 1], a00, a01, a02, a03, b2, b3);
            mma16816(acc[1][2 * vt],     a10, a11, a12, a13, b0, b1);
            mma16816(acc[1][2 * vt + 1], a10, a11, a12, a13, b2, b3);
        }
    }
}

static __device__ __forceinline__ void zero4(float acc[2][4][4]) {
    #pragma unroll
    for (int m = 0; m < 2; ++m)
        #pragma unroll
        for (int n = 0; n < 4; ++n)
            #pragma unroll
            for (int j = 0; j < 4; ++j) acc[m][n][j] = 0.f;
}

__global__ __launch_bounds__(NTHREADS, 2)
void ffm_main(const float* __restrict__ w, float* __restrict__ out) {
    extern __shared__ char smem[];
    const uint32_t sb = smem_u32(smem);
    const int tid = threadIdx.x;
    const int wrp = tid >> 5;
    const int lane = tid & 31;
    const int p = wrp >> 1;          // pair (m-tile) 0..3
    const int h = wrp & 1;           // n-half 0..1
    const int r0 = blockIdx.x * ROWT;
    float* dks = (float*)(smem + SM_DKS);

    const int bar_p = 1 + p, bar_h = 5 + h;

    float acc_int[4] = {0.f, 0.f, 0.f, 0.f};   // row = p*32 + (lane>>2) + slot*8

    for (int uu = 0; uu < 4; ++uu) {
        const int u = blockIdx.y * 4 + uu;
        const int s = U_S[u], t = U_T[u];
        const __half* xs = g_xh + (size_t)r0 * NFEAT + s * FDIM;
        const __half* xt = g_xh + (size_t)r0 * NFEAT + t * FDIM;
        const __half* vst = g_vh + (size_t)((s * NFIELDS + t) * NL + h * 32) * FDIM;
        const __half* vts = g_vh + (size_t)((t * NFIELDS + s) * NL + h * 32) * FDIM;

        float a1[2][4][4];
        zero4(a1);
        float p4[4] = {0.f, 0.f, 0.f, 0.f};

        if (s != t) {
            float a2[2][4][4];
            zero4(a2);
            // prologue: quarters 0,1
            #pragma unroll
            for (int q = 0; q < 2; ++q) {
                load_xq(sb + SM_XS + q * 16384, xs + q * 64, p, h, lane);
                load_xq(sb + SM_XT + q * 16384, xt + q * 64, p, h, lane);
                load_vq(sb + SM_VS + (q * 2 + h) * 4096, vst + q * 64, p, lane);
                load_vq(sb + SM_VT + (q * 2 + h) * 4096, vts + q * 64, p, lane);
                CP_COMMIT();
            }
            #pragma unroll
            for (int q = 0; q < 4; ++q) {
                if (q == 3) { CP_WAIT0(); } else { CP_WAIT1(); }
                __syncwarp();
                BARX(bar_p, 64); BARX(bar_h, 128);      // quarter q visible everywhere
                const int bf = q & 1;
                gemm32(sb + SM_XS + bf * 16384, sb + SM_VS + (bf * 2 + h) * 4096, p, lane, a1);
                gemm32(sb + SM_XT + bf * 16384, sb + SM_VT + (bf * 2 + h) * 4096, p, lane, a2);
                if (q < 2) {
                    BARX(bar_p, 64); BARX(bar_h, 128);  // co-owners done reading buf
                    load_xq(sb + SM_XS + bf * 16384, xs + (q + 2) * 64, p, h, lane);
                    load_xq(sb + SM_XT + bf * 16384, xt + (q + 2) * 64, p, h, lane);
                    load_vq(sb + SM_VS + (bf * 2 + h) * 4096, vst + (q + 2) * 64, p, lane);
                    load_vq(sb + SM_VT + (bf * 2 + h) * 4096, vts + (q + 2) * 64, p, lane);
                    CP_COMMIT();
                }
            }
            // dot(M1, M2) over this warp's n-half, counted twice (ordered pairs)
            #pragma unroll
            for (int mf = 0; mf < 2; ++mf)
                #pragma unroll
                for (int nf = 0; nf < 4; ++nf) {
                    p4[mf * 2 + 0] += a1[mf][nf][0] * a2[mf][nf][0] +
                                      a1[mf][nf][1] * a2[mf][nf][1];
                    p4[mf * 2 + 1] += a1[mf][nf][2] * a2[mf][nf][2] +
                                      a1[mf][nf][3] * a2[mf][nf][3];
                }
            #pragma unroll
            for (int i = 0; i < 4; ++i) p4[i] *= 2.f;
        } else {
            // ---- diag unit ----
            // dks[k] = sum_l V_ss[l,k]^2 from global fp16 (same values the GEMM uses)
            {
                const __half* vp = g_vh + (size_t)((s * NFIELDS + s) * NL) * FDIM + tid;
                float a = 0.f;
                #pragma unroll 8
                for (int l = 0; l < NL; ++l) {
                    float f = __half2float(vp[l * FDIM]);
                    a += f * f;
                }
                dks[tid] = a;
            }
            __syncthreads();

            #pragma unroll
            for (int q = 0; q < 2; ++q) {
                load_xq(sb + SM_XS + q * 16384, xs + q * 64, p, h, lane);
                load_vq(sb + SM_VS + (q * 2 + h) * 4096, vst + q * 64, p, lane);
                CP_COMMIT();
            }
            float dql[4] = {0.f, 0.f, 0.f, 0.f};
            const float* wp = w + s * FDIM;
            #pragma unroll
            for (int q = 0; q < 4; ++q) {
                if (q == 3) { CP_WAIT0(); } else { CP_WAIT1(); }
                __syncwarp();
                __syncthreads();                         // quarter visible (X pair + V halves)
                const int bf = q & 1;
                gemm32(sb + SM_XS + bf * 16384, sb + SM_VS + (bf * 2 + h) * 4096, p, lane, a1);
                // q + linear for this quarter (k-split by h, rows of own pair)
                {
                    const char* xsm = smem + SM_XS + bf * 16384;
                    const int kin0 = h * 32 + (lane & 3) * 8;
                    const int rb = p * 32 + (lane >> 2);
                    const float* dq = dks + q * 64;
                    const float* wq = wp + q * 64;
                    #pragma unroll
                    for (int i = 0; i < 8; ++i) {
                        int k = kin0 + i;
                        float dk = dq[k];
                        float wv = __ldg(wq + k);
                        #pragma unroll
                        for (int sl = 0; sl < 4; ++sl) {
                            float xv = __half2float(*(const __half*)(
                                xsm + SW128((rb + sl * 8) * 128 + k * 2)));
                            dql[sl] += xv * (4.f * wv - xv * dk);
                        }
                    }
                }
                BARX(bar_p, 64); BARX(bar_h, 128);       // pair done qlin/gemm, h done gemm
                if (q < 2) {
                    load_xq(sb + SM_XS + bf * 16384, xs + (q + 2) * 64, p, h, lane);
                    load_vq(sb + SM_VS + (bf * 2 + h) * 4096, vst + (q + 2) * 64, p, lane);
                    CP_COMMIT();
                }
            }
            // self dot - q + 4*linear
            #pragma unroll
            for (int mf = 0; mf < 2; ++mf)
                #pragma unroll
                for (int nf = 0; nf < 4; ++nf) {
                    p4[mf * 2 + 0] += a1[mf][nf][0] * a1[mf][nf][0] +
                                      a1[mf][nf][1] * a1[mf][nf][1];
                    p4[mf * 2 + 1] += a1[mf][nf][2] * a1[mf][nf][2] +
                                      a1[mf][nf][3] * a1[mf][nf][3];
                }
            #pragma unroll
            for (int i = 0; i < 4; ++i) p4[i] += dql[i];
        }

        // reduce over 4 lanes sharing each row; accumulate
        #pragma unroll
        for (int i = 0; i < 4; ++i) {
            p4[i] += __shfl_xor_sync(0xFFFFFFFFu, p4[i], 1);
            p4[i] += __shfl_xor_sync(0xFFFFFFFFu, p4[i], 2);
            acc_int[i] += p4[i];
        }
        // unit-end: free all buffers for next unit's prologue
        BARX(bar_p, 64); BARX(bar_h, 128);
    }

    if ((lane & 3) == 0) {
        #pragma unroll
        for (int sl = 0; sl < 4; ++sl) {
            int row = r0 + p * 32 + (lane >> 2) + sl * 8;
            atomicAdd(out + row, 0.25f * acc_int[sl]);
        }
    }
}

// ------------------------------------------------------------------
extern "C" void kernel_launch(void* const* d_in, const int* in_sizes, int n_in,
                              void* d_out, int out_size) {
    const float* x = (const float*)d_in[0];
    const float* b = (const float*)d_in[1];
    const float* w = (const float*)d_in[2];
    const float* V = (const float*)d_in[3];
    float* out = (float*)d_out;

    cudaFuncSetAttribute(ffm_main, cudaFuncAttributeMaxDynamicSharedMemorySize, SM_TOTAL);

    {
        size_t n8 = (size_t)NBATCH * NFEAT / 8;
        k_convert_x<<<(unsigned)((n8 + 255) / 256), 256>>>(x);
    }
    k_convert_v<<<(NFEAT * NFIELDS * NL + 255) / 256, 256>>>(V, b, out);
    ffm_main<<<dim3(NBATCH / ROWT, 9), NTHREADS, SM_TOTAL>>>(w, out);
}